// round 10
// baseline (speedup 1.0000x reference)
#include <cuda_runtime.h>
#include <cuda_fp16.h>
#include <math.h>
#include <stdint.h>

#define BQ 32
#define TQ 1024
#define DQ 1024
#define SQ 128
#define HQ 4096
#define MQ (BQ * TQ)

// ---- scratch ----
__device__ __align__(16) __half g_lnx_hi[(size_t)MQ * DQ];
__device__ __align__(16) __half g_lnx_lo[(size_t)MQ * DQ];
__device__ __align__(16) float  g_inj[(size_t)MQ * SQ];
__device__ __align__(16) __half g_h_hi[(size_t)MQ * SQ];
__device__ __align__(16) __half g_h_lo[(size_t)MQ * SQ];
__device__ __align__(16) __half g_x2_hi[(size_t)MQ * DQ];
__device__ __align__(16) __half g_hb_hi[(size_t)MQ * HQ];
__device__ __align__(16) __half g_x3_hi[(size_t)MQ * DQ];
__device__ __align__(16) __half g_wi_hi[SQ * DQ], g_wi_lo[SQ * DQ];
__device__ __align__(16) __half g_ro_hi[DQ * SQ];
__device__ __align__(16) __half g_w1_hi[(size_t)HQ * DQ];
__device__ __align__(16) __half g_w2_hi[(size_t)DQ * HQ];

// ---- helpers ----
__device__ __forceinline__ uint32_t smem_u32(const void* p) {
    uint32_t a;
    asm("{ .reg .u64 t; cvta.to.shared.u64 t, %1; cvt.u32.u64 %0, t; }" : "=r"(a) : "l"(p));
    return a;
}
__device__ __forceinline__ void cpa16(uint32_t s, const void* g) {
    asm volatile("cp.async.cg.shared.global [%0], [%1], 16;" :: "r"(s), "l"(g) : "memory");
}
template <int N>
__device__ __forceinline__ void wgrp() {
    asm volatile("cp.async.wait_group %0;" :: "n"(N) : "memory");
}
__device__ __forceinline__ void ldsm4(uint32_t& r0, uint32_t& r1, uint32_t& r2, uint32_t& r3, uint32_t a) {
    asm volatile("ldmatrix.sync.aligned.m8n8.x4.shared.b16 {%0,%1,%2,%3}, [%4];"
                 : "=r"(r0), "=r"(r1), "=r"(r2), "=r"(r3) : "r"(a));
}
__device__ __forceinline__ void mma16816(float* c, const uint32_t* a, const uint32_t* b) {
    asm volatile("mma.sync.aligned.m16n8k16.row.col.f32.f16.f16.f32 "
                 "{%0,%1,%2,%3}, {%4,%5,%6,%7}, {%8,%9}, {%0,%1,%2,%3};"
                 : "+f"(c[0]), "+f"(c[1]), "+f"(c[2]), "+f"(c[3])
                 : "r"(a[0]), "r"(a[1]), "r"(a[2]), "r"(a[3]), "r"(b[0]), "r"(b[1]));
}
__device__ __forceinline__ uint32_t pkh2(float a, float b) {
    __half2 t = __floats2half2_rn(a, b);
    return *reinterpret_cast<uint32_t*>(&t);
}
__device__ __forceinline__ unsigned long long pk2(float lo, float hi) {
    unsigned long long r;
    asm("mov.b64 %0, {%1, %2};" : "=l"(r) : "r"(__float_as_uint(lo)), "r"(__float_as_uint(hi)));
    return r;
}
__device__ __forceinline__ void fma2(unsigned long long& d, unsigned long long a, unsigned long long b) {
    asm("fma.rn.f32x2 %0, %1, %2, %3;" : "=l"(d) : "l"(a), "l"(b), "l"(d));
}
__device__ __forceinline__ float gelu_exact(float x) {
    return 0.5f * x * (1.0f + erff(x * 0.7071067811865476f));
}
__device__ __forceinline__ void split_store2(__half* ohi, __half* olo, size_t off, float v0, float v1) {
    __half h0 = __float2half_rn(v0), h1 = __float2half_rn(v1);
    float l0 = v0 - __half2float(h0), l1 = v1 - __half2float(h1);
    *reinterpret_cast<uint32_t*>(ohi + off) = pkh2(__half2float(h0), __half2float(h1));
    *reinterpret_cast<uint32_t*>(olo + off) = pkh2(l0, l1);
}
__device__ __forceinline__ float2 unpkh2(uint32_t u) {
    __half2 h = *reinterpret_cast<__half2*>(&u);
    return __half22float2(h);
}

// ---- conversions ----
__global__ __launch_bounds__(256)
void conv_split(const float* __restrict__ in, __half* __restrict__ hi,
                __half* __restrict__ lo) {
    size_t idx = ((size_t)blockIdx.x * blockDim.x + threadIdx.x) * 8;
    const float4* p = reinterpret_cast<const float4*>(in + idx);
    float4 a = p[0], b = p[1];
    float v[8] = { a.x, a.y, a.z, a.w, b.x, b.y, b.z, b.w };
    float hf[8], lf[8];
    #pragma unroll
    for (int i = 0; i < 8; ++i) {
        __half h = __float2half_rn(v[i]);
        hf[i] = __half2float(h);
        lf[i] = v[i] - hf[i];
    }
    uint4 H = { pkh2(hf[0], hf[1]), pkh2(hf[2], hf[3]), pkh2(hf[4], hf[5]), pkh2(hf[6], hf[7]) };
    uint4 L = { pkh2(lf[0], lf[1]), pkh2(lf[2], lf[3]), pkh2(lf[4], lf[5]), pkh2(lf[6], lf[7]) };
    *reinterpret_cast<uint4*>(hi + idx) = H;
    *reinterpret_cast<uint4*>(lo + idx) = L;
}

__global__ __launch_bounds__(256)
void conv_hi(const float* __restrict__ in, __half* __restrict__ hi) {
    size_t idx = ((size_t)blockIdx.x * blockDim.x + threadIdx.x) * 8;
    const float4* p = reinterpret_cast<const float4*>(in + idx);
    float4 a = p[0], b = p[1];
    uint4 H = { pkh2(a.x, a.y), pkh2(a.z, a.w), pkh2(b.x, b.y), pkh2(b.z, b.w) };
    *reinterpret_cast<uint4*>(hi + idx) = H;
}

// ---- LayerNorm ----
__device__ __forceinline__ void block_reduce2(float& a, float& b) {
    #pragma unroll
    for (int o = 16; o > 0; o >>= 1) {
        a += __shfl_xor_sync(0xFFFFFFFFu, a, o);
        b += __shfl_xor_sync(0xFFFFFFFFu, b, o);
    }
    __shared__ float sa[8], sb[8];
    int w = threadIdx.x >> 5, l = threadIdx.x & 31;
    if (l == 0) { sa[w] = a; sb[w] = b; }
    __syncthreads();
    if (w == 0) {
        a = (l < 8) ? sa[l] : 0.f;
        b = (l < 8) ? sb[l] : 0.f;
        #pragma unroll
        for (int o = 4; o > 0; o >>= 1) {
            a += __shfl_xor_sync(0xFFFFFFFFu, a, o);
            b += __shfl_xor_sync(0xFFFFFFFFu, b, o);
        }
        if (l == 0) { sa[0] = a; sb[0] = b; }
    }
    __syncthreads();
    a = sa[0]; b = sb[0];
}

// LN1: fp32 in -> hi/lo fp16 out
__global__ __launch_bounds__(256)
void ln1_kernel(const float* __restrict__ x, const float* __restrict__ w,
                const float* __restrict__ bias,
                __half* __restrict__ ohi, __half* __restrict__ olo) {
    size_t row = blockIdx.x;
    float4 v = reinterpret_cast<const float4*>(x + row * DQ)[threadIdx.x];
    float s = v.x + v.y + v.z + v.w;
    float s2 = v.x * v.x + v.y * v.y + v.z * v.z + v.w * v.w;
    block_reduce2(s, s2);
    float mean = s * (1.0f / DQ);
    float rs = rsqrtf(s2 * (1.0f / DQ) - mean * mean + 1e-5f);
    float4 wv = reinterpret_cast<const float4*>(w)[threadIdx.x];
    float4 bv = reinterpret_cast<const float4*>(bias)[threadIdx.x];
    float4 o;
    o.x = (v.x - mean) * rs * wv.x + bv.x;
    o.y = (v.y - mean) * rs * wv.y + bv.y;
    o.z = (v.z - mean) * rs * wv.z + bv.z;
    o.w = (v.w - mean) * rs * wv.w + bv.w;
    size_t off = row * DQ + 4 * threadIdx.x;
    split_store2(ohi, olo, off, o.x, o.y);
    split_store2(ohi, olo, off + 2, o.z, o.w);
}

// LN2: fp16 in -> out = x + LN(x) fp32
__global__ __launch_bounds__(256)
void ln2_kernel(const __half* __restrict__ x, const float* __restrict__ w,
                const float* __restrict__ bias, float* __restrict__ out) {
    size_t row = blockIdx.x;
    uint2 r = reinterpret_cast<const uint2*>(x + row * DQ)[threadIdx.x];
    float2 a0 = unpkh2(r.x), a1 = unpkh2(r.y);
    float v0 = a0.x, v1 = a0.y, v2 = a1.x, v3 = a1.y;
    float s = v0 + v1 + v2 + v3;
    float s2 = v0 * v0 + v1 * v1 + v2 * v2 + v3 * v3;
    block_reduce2(s, s2);
    float mean = s * (1.0f / DQ);
    float rs = rsqrtf(s2 * (1.0f / DQ) - mean * mean + 1e-5f);
    float4 wv = reinterpret_cast<const float4*>(w)[threadIdx.x];
    float4 bv = reinterpret_cast<const float4*>(bias)[threadIdx.x];
    float4 o;
    o.x = (v0 - mean) * rs * wv.x + bv.x + v0;
    o.y = (v1 - mean) * rs * wv.y + bv.y + v1;
    o.z = (v2 - mean) * rs * wv.z + bv.z + v2;
    o.w = (v3 - mean) * rs * wv.w + bv.w + v3;
    reinterpret_cast<float4*>(out + row * DQ)[threadIdx.x] = o;
}

// ---- scan: 512 threads, 4-way k split, register weights ----
__global__ __launch_bounds__(512)
void scan_kernel(const float* __restrict__ gate_w, const float* __restrict__ gate_b,
                 const float* __restrict__ state_flow, const float* __restrict__ inj,
                 __half* __restrict__ hhi, __half* __restrict__ hlo) {
    __shared__ __align__(8) float h[SQ];
    __shared__ __align__(8) unsigned long long part[512];
    const int tid = threadIdx.x;
    const int s = tid & 127;
    const int q = tid >> 7;
    const int b = blockIdx.x;

    unsigned long long wv[32];
    #pragma unroll
    for (int j = 0; j < 32; ++j) {
        int k = q * 32 + j;
        wv[j] = pk2(gate_w[s * SQ + k], state_flow[s * SQ + k]);
    }
    float gb = (q == 0) ? gate_b[s] : 0.0f;
    if (q == 0) h[s] = 0.0f;
    __syncthreads();

    const float* injb = inj + (size_t)b * TQ * SQ;
    for (int t = 0; t < TQ; ++t) {
        float injv = (q == 0) ? injb[(size_t)t * SQ + s] : 0.0f;
        unsigned long long acc2 = 0ull;
        const float2* h2 = reinterpret_cast<const float2*>(h + q * 32);
        #pragma unroll
        for (int j = 0; j < 16; ++j) {
            float2 hp = h2[j];
            fma2(acc2, pk2(hp.x, hp.x), wv[2 * j]);
            fma2(acc2, pk2(hp.y, hp.y), wv[2 * j + 1]);
        }
        part[tid] = acc2;
        __syncthreads();
        if (q == 0) {
            float2 p0 = *reinterpret_cast<float2*>(&part[s]);
            float2 p1 = *reinterpret_cast<float2*>(&part[s + 128]);
            float2 p2 = *reinterpret_cast<float2*>(&part[s + 256]);
            float2 p3 = *reinterpret_cast<float2*>(&part[s + 384]);
            float accg = p0.x + p1.x + p2.x + p3.x + gb + injv;
            float accf = p0.y + p1.y + p2.y + p3.y;
            float hold = h[s];
            float g = 1.0f / (1.0f + expf(-accg));
            float hn = (1.0f - g) * hold + g * accf;
            h[s] = hn;
            size_t off = ((size_t)(b << 10) + t) * SQ + s;
            __half hh = __float2half_rn(hn);
            hhi[off] = hh;
            hlo[off] = __float2half_rn(hn - __half2float(hh));
        }
        __syncthreads();
    }
}

// ---- narrow HMMA GEMM (128x128, 3-term, for inj) ----
#define ROWP 40
#define MATB (128 * ROWP * 2)
#define NGSM 122880

__global__ __launch_bounds__(256, 1)
void gemm_inj(const __half* __restrict__ Ahi, const __half* __restrict__ Alo,
              const __half* __restrict__ Bhi, const __half* __restrict__ Blo,
              float* __restrict__ outf, int K, int N) {
    constexpr int NSTG = 3;
    constexpr int STGB = 4 * MATB;
    extern __shared__ __align__(16) unsigned char dsm[];
    const uint32_t sbase = smem_u32(dsm);
    const int tid = threadIdx.x, lane = tid & 31, wid = tid >> 5;
    const size_t mBase = (size_t)blockIdx.y * 128, nBase = (size_t)blockIdx.x * 128;

    const int lrow = tid >> 1, lchunk = (tid & 1) * 2;
    const size_t aoff = (mBase + lrow) * (size_t)K + lchunk * 8;
    const size_t boff = (nBase + lrow) * (size_t)K + lchunk * 8;
    const uint32_t soff = (uint32_t)(lrow * 80 + lchunk * 16);
    const int ktiles = K / 32;

    auto issue = [&](int st, int kt) {
        uint32_t sb = sbase + (uint32_t)st * STGB;
        size_t k0 = (size_t)kt * 32;
        const __half* pa = Ahi + aoff + k0;
        const __half* pb = Alo + aoff + k0;
        const __half* pc = Bhi + boff + k0;
        const __half* pd = Blo + boff + k0;
        cpa16(sb + soff,            pa);  cpa16(sb + soff + 16,            pa + 8);
        cpa16(sb + MATB + soff,     pb);  cpa16(sb + MATB + soff + 16,     pb + 8);
        cpa16(sb + 2 * MATB + soff, pc);  cpa16(sb + 2 * MATB + soff + 16, pc + 8);
        cpa16(sb + 3 * MATB + soff, pd);  cpa16(sb + 3 * MATB + soff + 16, pd + 8);
        asm volatile("cp.async.commit_group;" ::: "memory");
    };
    for (int s = 0; s < 2; ++s) issue(s, s);

    const int wy = wid >> 2, wx = wid & 3;
    const int m_w = wy * 64, n_w = wx * 32;
    float acc[4][4][4];
    #pragma unroll
    for (int i = 0; i < 4; ++i)
        #pragma unroll
        for (int j = 0; j < 4; ++j)
            #pragma unroll
            for (int e = 0; e < 4; ++e) acc[i][j][e] = 0.0f;

    for (int kt = 0; kt < ktiles; ++kt) {
        if (ktiles - 1 - kt >= 1) wgrp<1>(); else wgrp<0>();
        __syncthreads();
        if (kt + 2 < ktiles) issue((kt + 2) % NSTG, kt + 2);
        const uint32_t sb = sbase + (uint32_t)(kt % NSTG) * STGB;
        const uint32_t sAh = sb, sAl = sb + MATB, sBh = sb + 2 * MATB, sBl = sb + 3 * MATB;
        #pragma unroll
        for (int kk = 0; kk < 2; ++kk) {
            const int kc = kk * 16;
            const int arow = (lane & 15);
            const int acol = kc + ((lane >> 4) << 3);
            const int brow = (lane & 7) + ((lane >> 4) << 3);
            const int bcol = kc + (lane & 8);
            uint32_t ah[4][4], al[4][4], bh[4][2], bl[4][2];
            #pragma unroll
            for (int mf = 0; mf < 4; ++mf) {
                uint32_t a = (uint32_t)((m_w + mf * 16 + arow) * ROWP + acol) * 2;
                ldsm4(ah[mf][0], ah[mf][1], ah[mf][2], ah[mf][3], sAh + a);
                ldsm4(al[mf][0], al[mf][1], al[mf][2], al[mf][3], sAl + a);
            }
            #pragma unroll
            for (int g = 0; g < 2; ++g) {
                uint32_t a = (uint32_t)((n_w + g * 16 + brow) * ROWP + bcol) * 2;
                uint32_t r0, r1, r2, r3;
                ldsm4(r0, r1, r2, r3, sBh + a);
                bh[g * 2][0] = r0; bh[g * 2][1] = r1; bh[g * 2 + 1][0] = r2; bh[g * 2 + 1][1] = r3;
                ldsm4(r0, r1, r2, r3, sBl + a);
                bl[g * 2][0] = r0; bl[g * 2][1] = r1; bl[g * 2 + 1][0] = r2; bl[g * 2 + 1][1] = r3;
            }
            #pragma unroll
            for (int mf = 0; mf < 4; ++mf)
                #pragma unroll
                for (int nf = 0; nf < 4; ++nf) {
                    mma16816(acc[mf][nf], ah[mf], bh[nf]);
                    mma16816(acc[mf][nf], al[mf], bh[nf]);
                    mma16816(acc[mf][nf], ah[mf], bl[nf]);
                }
        }
        __syncthreads();
    }
    #pragma unroll
    for (int mf = 0; mf < 4; ++mf)
        #pragma unroll
        for (int nf = 0; nf < 4; ++nf) {
            size_t r0 = mBase + m_w + mf * 16 + (lane >> 2);
            size_t cc = nBase + n_w + nf * 8 + (lane & 3) * 2;
            float2 s0 = { acc[mf][nf][0], acc[mf][nf][1] };
            float2 s1 = { acc[mf][nf][2], acc[mf][nf][3] };
            *reinterpret_cast<float2*>(outf + r0 * N + cc) = s0;
            *reinterpret_cast<float2*>(outf + (r0 + 8) * N + cc) = s1;
        }
}

// ---- x2 GEMM: 128x128, 2-term A, 3 stages, 2 CTA/SM ----
#define W_AB 10240
#define X2_STG (3 * W_AB)
#define X2_SMEM (3 * X2_STG)   // 92160

__global__ __launch_bounds__(256, 2)
void gemm_x2(const __half* __restrict__ Ahi, const __half* __restrict__ Alo,
             const __half* __restrict__ Bhi,
             const __half* __restrict__ exh, const __half* __restrict__ exl,
             __half* __restrict__ ohi, int K, int N) {
    constexpr int NSTG = 3;
    extern __shared__ __align__(16) unsigned char dsm[];
    const uint32_t sbase = smem_u32(dsm);
    const int tid = threadIdx.x, lane = tid & 31, wid = tid >> 5;
    const size_t mBase = (size_t)blockIdx.y * 128, nBase = (size_t)blockIdx.x * 128;

    const int lrow = tid >> 1, lchunk = (tid & 1) * 2;
    const size_t aoff = (mBase + lrow) * (size_t)K + lchunk * 8;
    const size_t boff = (nBase + lrow) * (size_t)K + lchunk * 8;
    const uint32_t soff = (uint32_t)(lrow * 80 + lchunk * 16);
    const int ktiles = K / 32;

    auto issue = [&](int st, int kt) {
        uint32_t sb = sbase + (uint32_t)st * X2_STG;
        size_t k0 = (size_t)kt * 32;
        const __half* pa = Ahi + aoff + k0;
        const __half* pb = Alo + aoff + k0;
        const __half* pc = Bhi + boff + k0;
        cpa16(sb + soff,            pa);  cpa16(sb + soff + 16,            pa + 8);
        cpa16(sb + W_AB + soff,     pb);  cpa16(sb + W_AB + soff + 16,     pb + 8);
        cpa16(sb + 2 * W_AB + soff, pc);  cpa16(sb + 2 * W_AB + soff + 16, pc + 8);
        asm volatile("cp.async.commit_group;" ::: "memory");
    };
    const int npre = ktiles < 2 ? ktiles : 2;
    for (int s = 0; s < npre; ++s) issue(s, s);

    const int wy = wid >> 2, wx = wid & 3;
    const int m_w = wy * 64, n_w = wx * 32;

    float acc[4][4][4];
    #pragma unroll
    for (int i = 0; i < 4; ++i)
        #pragma unroll
        for (int j = 0; j < 4; ++j)
            #pragma unroll
            for (int e = 0; e < 4; ++e) acc[i][j][e] = 0.0f;

    for (int kt = 0; kt < ktiles; ++kt) {
        if (ktiles - 1 - kt >= 1) wgrp<1>(); else wgrp<0>();
        __syncthreads();
        if (kt + 2 < ktiles) issue((kt + 2) % NSTG, kt + 2);

        const uint32_t sb = sbase + (uint32_t)(kt % NSTG) * X2_STG;
        const uint32_t sAh = sb, sAl = sb + W_AB, sBh = sb + 2 * W_AB;

        #pragma unroll
        for (int kk = 0; kk < 2; ++kk) {
            const int kc = kk * 16;
            const int arow = (lane & 15);
            const int acol = kc + ((lane >> 4) << 3);
            const int brow = (lane & 7) + ((lane >> 4) << 3);
            const int bcol = kc + (lane & 8);
            uint32_t ah[4][4], al[4][4], bh[4][2];
            #pragma unroll
            for (int mf = 0; mf < 4; ++mf) {
                uint32_t a = (uint32_t)((m_w + mf * 16 + arow) * ROWP + acol) * 2;
                ldsm4(ah[mf][0], ah[mf][1], ah[mf][2], ah[mf][3], sAh + a);
                ldsm4(al[mf][0], al[mf][1], al[mf][2], al[mf][3], sAl + a);
            }
            #pragma unroll
            for (int g = 0; g < 2; ++g) {
                uint32_t a = (uint32_t)((n_w + g * 16 + brow) * ROWP + bcol) * 2;
                uint32_t r0, r1, r2, r3;
                ldsm4(r0, r1, r2, r3, sBh + a);
                bh[g * 2][0] = r0; bh[g * 2][1] = r1; bh[g * 2 + 1][0] = r2; bh[g * 2 + 1][1] = r3;
            }
            #pragma unroll
            for (int mf = 0; mf < 4; ++mf)
                #pragma unroll
                for (int nf = 0; nf < 4; ++nf) {
                    mma16816(acc[mf][nf], ah[mf], bh[nf]);
                    mma16816(acc[mf][nf], al[mf], bh[nf]);
                }
        }
        __syncthreads();
    }

    #pragma unroll
    for (int mf = 0; mf < 4; ++mf) {
        #pragma unroll
        for (int nf = 0; nf < 4; ++nf) {
            size_t r0 = mBase + m_w + mf * 16 + (lane >> 2);
            size_t cc = nBase + n_w + nf * 8 + (lane & 3) * 2;
            float2 e0h = unpkh2(*reinterpret_cast<const uint32_t*>(exh + r0 * N + cc));
            float2 e0l = unpkh2(*reinterpret_cast<const uint32_t*>(exl + r0 * N + cc));
            float2 e1h = unpkh2(*reinterpret_cast<const uint32_t*>(exh + (r0 + 8) * N + cc));
            float2 e1l = unpkh2(*reinterpret_cast<const uint32_t*>(exl + (r0 + 8) * N + cc));
            float v0 = acc[mf][nf][0] + e0h.x + e0l.x;
            float v1 = acc[mf][nf][1] + e0h.y + e0l.y;
            float v2 = acc[mf][nf][2] + e1h.x + e1l.x;
            float v3 = acc[mf][nf][3] + e1h.y + e1l.y;
            *reinterpret_cast<uint32_t*>(ohi + r0 * N + cc) = pkh2(v0, v1);
            *reinterpret_cast<uint32_t*>(ohi + (r0 + 8) * N + cc) = pkh2(v2, v3);
        }
    }
}

// ---- 1-term HMMA GEMM (128x128, 5 stages, 2 CTAs/SM) ----
// GELU=true: +bias gelu; false: +bias. Output fp16 hi.
#define G1_STG (2 * W_AB)
#define G1_NSTG 5
#define G1_SMEM (G1_NSTG * G1_STG)   // 102400

template <bool GELU>
__global__ __launch_bounds__(256, 2)
void gemm1(const __half* __restrict__ A, const __half* __restrict__ B,
           const float* __restrict__ ext, __half* __restrict__ ohi, int K, int N) {
    extern __shared__ __align__(16) unsigned char dsm[];
    const uint32_t sbase = smem_u32(dsm);
    const int tid = threadIdx.x, lane = tid & 31, wid = tid >> 5;
    const size_t mBase = (size_t)blockIdx.y * 128, nBase = (size_t)blockIdx.x * 128;

    const int lrow = tid >> 1, lchunk = (tid & 1) * 2;
    const size_t aoff = (mBase + lrow) * (size_t)K + lchunk * 8;
    const size_t boff = (nBase + lrow) * (size_t)K + lchunk * 8;
    const uint32_t soff = (uint32_t)(lrow * 80 + lchunk * 16);
    const int ktiles = K / 32;

    auto issue = [&](int st, int kt) {
        uint32_t sb = sbase + (uint32_t)st * G1_STG;
        size_t k0 = (size_t)kt * 32;
        const __half* pa = A + aoff + k0;
        const __half* pb = B + boff + k0;
        cpa16(sb + soff,        pa);  cpa16(sb + soff + 16,        pa + 8);
        cpa16(sb + W_AB + soff, pb);  cpa16(sb + W_AB + soff + 16, pb + 8);
        asm volatile("cp.async.commit_group;" ::: "memory");
    };
    const int npre = ktiles < G1_NSTG - 1 ? ktiles : G1_NSTG - 1;
    for (int s = 0; s < npre; ++s) issue(s, s);

    const int wy = wid >> 2, wx = wid & 3;
    const int m_w = wy * 64, n_w = wx * 32;

    float acc[4][4][4];
    #pragma unroll
    for (int i = 0; i < 4; ++i)
        #pragma unroll
        for (int j = 0; j < 4; ++j)
            #pragma unroll
            for (int e = 0; e < 4; ++e) acc[i][j][e] = 0.0f;

    for (int kt = 0; kt < ktiles; ++kt) {
        const int rem = ktiles - 1 - kt;
        if (rem >= 3) wgrp<3>(); else if (rem == 2) wgrp<2>();
        else if (rem == 1) wgrp<1>(); else wgrp<0>();
        __syncthreads();
        if (kt + G1_NSTG - 1 < ktiles) issue((kt + G1_NSTG - 1) % G1_NSTG, kt + G1_NSTG - 1);

        const uint32_t sb = sbase + (uint32_t)(kt % G1_NSTG) * G1_STG;
        const uint32_t sA = sb, sB = sb + W_AB;

        #pragma unroll
        for (int kk = 0; kk < 2; ++kk) {
            const int kc = kk * 16;
            const int arow = (lane & 15);
            const int acol = kc + ((lane >> 4) << 3);
            const int brow = (lane & 7) + ((lane >> 4) << 3);
            const int bcol = kc + (lane & 8);
            uint32_t ah[4][4], bh[4][2];
            #pragma unroll
            for (int mf = 0; mf < 4; ++mf) {
                uint32_t a = (uint32_t)((m_w + mf * 16 + arow) * ROWP + acol) * 2;
                ldsm4(ah[mf][0], ah[mf][1], ah[mf][2], ah[mf][3], sA + a);
            }
            #pragma unroll
            for (int g = 0; g < 2; ++g) {
                uint32_t a = (uint32_t)((n_w + g * 16 + brow) * ROWP + bcol) * 2;
                uint32_t r0, r1, r2, r3;
                ldsm4(r0, r1, r2, r3, sB + a);
                bh[g * 2][0] = r0; bh[g * 2][1] = r1; bh[g * 2 + 1][0] = r2; bh[g * 2 + 1][1] = r3;
            }
            #pragma unroll
            for (int mf = 0; mf < 4; ++mf)
                #pragma unroll
                for (int nf = 0; nf < 4; ++nf)
                    mma16816(acc[mf][nf], ah[mf], bh[nf]);
        }
        __syncthreads();
    }

    #pragma unroll
    for (int mf = 0; mf < 4; ++mf) {
        #pragma unroll
        for (int nf = 0; nf < 4; ++nf) {
            size_t r0 = mBase + m_w + mf * 16 + (lane >> 2);
            size_t cc = nBase + n_w + nf * 8 + (lane & 3) * 2;
            float2 bb = *reinterpret_cast<const float2*>(ext + cc);
            float v0 = acc[mf][nf][0] + bb.x, v1 = acc[mf][nf][1] + bb.y;
            float v2 = acc[mf][nf][2] + bb.x, v3 = acc[mf][nf][3] + bb.y;
            if (GELU) {
                v0 = gelu_exact(v0); v1 = gelu_exact(v1);
                v2 = gelu_exact(v2); v3 = gelu_exact(v3);
            }
            *reinterpret_cast<uint32_t*>(ohi + r0 * N + cc) = pkh2(v0, v1);
            *reinterpret_cast<uint32_t*>(ohi + (r0 + 8) * N + cc) = pkh2(v2, v3);
        }
    }
}

// ---- launch ----
extern "C" void kernel_launch(void* const* d_in, const int* in_sizes, int n_in,
                              void* d_out, int out_size) {
    const float* x          = (const float*)d_in[0];
    const float* ln1_w      = (const float*)d_in[1];
    const float* ln1_b      = (const float*)d_in[2];
    const float* state_flow = (const float*)d_in[3];
    const float* injection  = (const float*)d_in[4];
    const float* readout    = (const float*)d_in[5];
    const float* gate_w     = (const float*)d_in[6];
    const float* gate_b     = (const float*)d_in[7];
    const float* w1         = (const float*)d_in[8];
    const float* b1         = (const float*)d_in[9];
    const float* w2         = (const float*)d_in[10];
    const float* b2         = (const float*)d_in[11];
    const float* ln2_w      = (const float*)d_in[12];
    const float* ln2_b      = (const float*)d_in[13];
    float* out = (float*)d_out;

    float *inj;
    __half *lnxh, *lnxl, *hh, *hl, *x2h, *hbh, *x3h;
    __half *wih, *wil, *roh, *w1h, *w2h;
    cudaGetSymbolAddress((void**)&lnxh, g_lnx_hi);
    cudaGetSymbolAddress((void**)&lnxl, g_lnx_lo);
    cudaGetSymbolAddress((void**)&inj, g_inj);
    cudaGetSymbolAddress((void**)&hh, g_h_hi);
    cudaGetSymbolAddress((void**)&hl, g_h_lo);
    cudaGetSymbolAddress((void**)&x2h, g_x2_hi);
    cudaGetSymbolAddress((void**)&hbh, g_hb_hi);
    cudaGetSymbolAddress((void**)&x3h, g_x3_hi);
    cudaGetSymbolAddress((void**)&wih, g_wi_hi);
    cudaGetSymbolAddress((void**)&wil, g_wi_lo);
    cudaGetSymbolAddress((void**)&roh, g_ro_hi);
    cudaGetSymbolAddress((void**)&w1h, g_w1_hi);
    cudaGetSymbolAddress((void**)&w2h, g_w2_hi);

    cudaFuncSetAttribute(gemm_inj,     cudaFuncAttributeMaxDynamicSharedMemorySize, NGSM);
    cudaFuncSetAttribute(gemm_x2,      cudaFuncAttributeMaxDynamicSharedMemorySize, X2_SMEM);
    cudaFuncSetAttribute(gemm1<true>,  cudaFuncAttributeMaxDynamicSharedMemorySize, G1_SMEM);
    cudaFuncSetAttribute(gemm1<false>, cudaFuncAttributeMaxDynamicSharedMemorySize, G1_SMEM);

    // weight conversions
    conv_split<<<(SQ * DQ / 8) / 256, 256>>>(injection, wih, wil);
    conv_hi<<<(DQ * SQ / 8) / 256, 256>>>(readout, roh);
    conv_hi<<<(int)(((size_t)HQ * DQ / 8) / 256), 256>>>(w1, w1h);
    conv_hi<<<(int)(((size_t)DQ * HQ / 8) / 256), 256>>>(w2, w2h);
    // LN1 -> hi/lo
    ln1_kernel<<<MQ, 256>>>(x, ln1_w, ln1_b, lnxh, lnxl);
    // inj = lnx @ injection^T  (3-term)
    gemm_inj<<<dim3(1, MQ / 128), 256, NGSM>>>(lnxh, lnxl, wih, wil, inj, DQ, SQ);
    // scan -> h hi/lo
    scan_kernel<<<BQ, 512>>>(gate_w, gate_b, state_flow, inj, hh, hl);
    // x2 = (lnx_hi+lnx_lo) + h @ readout^T  (2-term A, 2 CTA/SM)
    gemm_x2<<<dim3(DQ / 128, MQ / 128), 256, X2_SMEM>>>(hh, hl, roh, lnxh, lnxl, x2h, SQ, DQ);
    // hb = gelu(x2 @ w1^T + b1)  (1-term, 5 stages, 2 CTA/SM)
    gemm1<true><<<dim3(HQ / 128, MQ / 128), 256, G1_SMEM>>>(x2h, w1h, b1, hbh, DQ, HQ);
    // x3 = hb @ w2^T + b2        (1-term, fp16 store)
    gemm1<false><<<dim3(DQ / 128, MQ / 128), 256, G1_SMEM>>>(hbh, w2h, b2, x3h, HQ, DQ);
    // out = x3 + LN(x3)
    ln2_kernel<<<MQ, 256>>>(x3h, ln2_w, ln2_b, out);
}

// round 11
// speedup vs baseline: 1.0165x; 1.0165x over previous
#include <cuda_runtime.h>
#include <cuda_fp16.h>
#include <math.h>
#include <stdint.h>

#define BQ 32
#define TQ 1024
#define DQ 1024
#define SQ 128
#define HQ 4096
#define MQ (BQ * TQ)

// ---- scratch ----
__device__ __align__(16) __half g_lnx_hi[(size_t)MQ * DQ];
__device__ __align__(16) __half g_lnx_lo[(size_t)MQ * DQ];
__device__ __align__(16) float  g_inj[(size_t)MQ * SQ];
__device__ __align__(16) __half g_h_hi[(size_t)MQ * SQ];
__device__ __align__(16) __half g_h_lo[(size_t)MQ * SQ];
__device__ __align__(16) __half g_x2_hi[(size_t)MQ * DQ];
__device__ __align__(16) __half g_hb_hi[(size_t)MQ * HQ];
__device__ __align__(16) __half g_x3_hi[(size_t)MQ * DQ];
__device__ __align__(16) __half g_wi_hi[SQ * DQ], g_wi_lo[SQ * DQ];
__device__ __align__(16) __half g_ro_hi[DQ * SQ];
__device__ __align__(16) __half g_w1_hi[(size_t)HQ * DQ];
__device__ __align__(16) __half g_w2_hi[(size_t)DQ * HQ];

// ---- helpers ----
__device__ __forceinline__ uint32_t smem_u32(const void* p) {
    uint32_t a;
    asm("{ .reg .u64 t; cvta.to.shared.u64 t, %1; cvt.u32.u64 %0, t; }" : "=r"(a) : "l"(p));
    return a;
}
__device__ __forceinline__ void cpa16(uint32_t s, const void* g) {
    asm volatile("cp.async.cg.shared.global [%0], [%1], 16;" :: "r"(s), "l"(g) : "memory");
}
template <int N>
__device__ __forceinline__ void wgrp() {
    asm volatile("cp.async.wait_group %0;" :: "n"(N) : "memory");
}
__device__ __forceinline__ void ldsm4(uint32_t& r0, uint32_t& r1, uint32_t& r2, uint32_t& r3, uint32_t a) {
    asm volatile("ldmatrix.sync.aligned.m8n8.x4.shared.b16 {%0,%1,%2,%3}, [%4];"
                 : "=r"(r0), "=r"(r1), "=r"(r2), "=r"(r3) : "r"(a));
}
__device__ __forceinline__ void mma16816(float* c, const uint32_t* a, const uint32_t* b) {
    asm volatile("mma.sync.aligned.m16n8k16.row.col.f32.f16.f16.f32 "
                 "{%0,%1,%2,%3}, {%4,%5,%6,%7}, {%8,%9}, {%0,%1,%2,%3};"
                 : "+f"(c[0]), "+f"(c[1]), "+f"(c[2]), "+f"(c[3])
                 : "r"(a[0]), "r"(a[1]), "r"(a[2]), "r"(a[3]), "r"(b[0]), "r"(b[1]));
}
__device__ __forceinline__ uint32_t pkh2(float a, float b) {
    __half2 t = __floats2half2_rn(a, b);
    return *reinterpret_cast<uint32_t*>(&t);
}
__device__ __forceinline__ unsigned long long pk2(float lo, float hi) {
    unsigned long long r;
    asm("mov.b64 %0, {%1, %2};" : "=l"(r) : "r"(__float_as_uint(lo)), "r"(__float_as_uint(hi)));
    return r;
}
__device__ __forceinline__ void fma2(unsigned long long& d, unsigned long long a, unsigned long long b) {
    asm("fma.rn.f32x2 %0, %1, %2, %3;" : "=l"(d) : "l"(a), "l"(b), "l"(d));
}
__device__ __forceinline__ float gelu_exact(float x) {
    return 0.5f * x * (1.0f + erff(x * 0.7071067811865476f));
}
__device__ __forceinline__ void split_store2(__half* ohi, __half* olo, size_t off, float v0, float v1) {
    __half h0 = __float2half_rn(v0), h1 = __float2half_rn(v1);
    float l0 = v0 - __half2float(h0), l1 = v1 - __half2float(h1);
    *reinterpret_cast<uint32_t*>(ohi + off) = pkh2(__half2float(h0), __half2float(h1));
    *reinterpret_cast<uint32_t*>(olo + off) = pkh2(l0, l1);
}
__device__ __forceinline__ float2 unpkh2(uint32_t u) {
    __half2 h = *reinterpret_cast<__half2*>(&u);
    return __half22float2(h);
}

// ---- conversions ----
__global__ __launch_bounds__(256)
void conv_split(const float* __restrict__ in, __half* __restrict__ hi,
                __half* __restrict__ lo) {
    size_t idx = ((size_t)blockIdx.x * blockDim.x + threadIdx.x) * 8;
    const float4* p = reinterpret_cast<const float4*>(in + idx);
    float4 a = p[0], b = p[1];
    float v[8] = { a.x, a.y, a.z, a.w, b.x, b.y, b.z, b.w };
    float hf[8], lf[8];
    #pragma unroll
    for (int i = 0; i < 8; ++i) {
        __half h = __float2half_rn(v[i]);
        hf[i] = __half2float(h);
        lf[i] = v[i] - hf[i];
    }
    uint4 H = { pkh2(hf[0], hf[1]), pkh2(hf[2], hf[3]), pkh2(hf[4], hf[5]), pkh2(hf[6], hf[7]) };
    uint4 L = { pkh2(lf[0], lf[1]), pkh2(lf[2], lf[3]), pkh2(lf[4], lf[5]), pkh2(lf[6], lf[7]) };
    *reinterpret_cast<uint4*>(hi + idx) = H;
    *reinterpret_cast<uint4*>(lo + idx) = L;
}

__global__ __launch_bounds__(256)
void conv_hi(const float* __restrict__ in, __half* __restrict__ hi) {
    size_t idx = ((size_t)blockIdx.x * blockDim.x + threadIdx.x) * 8;
    const float4* p = reinterpret_cast<const float4*>(in + idx);
    float4 a = p[0], b = p[1];
    uint4 H = { pkh2(a.x, a.y), pkh2(a.z, a.w), pkh2(b.x, b.y), pkh2(b.z, b.w) };
    *reinterpret_cast<uint4*>(hi + idx) = H;
}

// ---- LayerNorm ----
__device__ __forceinline__ void block_reduce2(float& a, float& b) {
    #pragma unroll
    for (int o = 16; o > 0; o >>= 1) {
        a += __shfl_xor_sync(0xFFFFFFFFu, a, o);
        b += __shfl_xor_sync(0xFFFFFFFFu, b, o);
    }
    __shared__ float sa[8], sb[8];
    int w = threadIdx.x >> 5, l = threadIdx.x & 31;
    if (l == 0) { sa[w] = a; sb[w] = b; }
    __syncthreads();
    if (w == 0) {
        a = (l < 8) ? sa[l] : 0.f;
        b = (l < 8) ? sb[l] : 0.f;
        #pragma unroll
        for (int o = 4; o > 0; o >>= 1) {
            a += __shfl_xor_sync(0xFFFFFFFFu, a, o);
            b += __shfl_xor_sync(0xFFFFFFFFu, b, o);
        }
        if (l == 0) { sa[0] = a; sb[0] = b; }
    }
    __syncthreads();
    a = sa[0]; b = sb[0];
}

// LN1: fp32 in -> hi/lo fp16 out
__global__ __launch_bounds__(256)
void ln1_kernel(const float* __restrict__ x, const float* __restrict__ w,
                const float* __restrict__ bias,
                __half* __restrict__ ohi, __half* __restrict__ olo) {
    size_t row = blockIdx.x;
    float4 v = reinterpret_cast<const float4*>(x + row * DQ)[threadIdx.x];
    float s = v.x + v.y + v.z + v.w;
    float s2 = v.x * v.x + v.y * v.y + v.z * v.z + v.w * v.w;
    block_reduce2(s, s2);
    float mean = s * (1.0f / DQ);
    float rs = rsqrtf(s2 * (1.0f / DQ) - mean * mean + 1e-5f);
    float4 wv = reinterpret_cast<const float4*>(w)[threadIdx.x];
    float4 bv = reinterpret_cast<const float4*>(bias)[threadIdx.x];
    float4 o;
    o.x = (v.x - mean) * rs * wv.x + bv.x;
    o.y = (v.y - mean) * rs * wv.y + bv.y;
    o.z = (v.z - mean) * rs * wv.z + bv.z;
    o.w = (v.w - mean) * rs * wv.w + bv.w;
    size_t off = row * DQ + 4 * threadIdx.x;
    split_store2(ohi, olo, off, o.x, o.y);
    split_store2(ohi, olo, off + 2, o.z, o.w);
}

// LN2: fp16 in -> out = x + LN(x) fp32
__global__ __launch_bounds__(256)
void ln2_kernel(const __half* __restrict__ x, const float* __restrict__ w,
                const float* __restrict__ bias, float* __restrict__ out) {
    size_t row = blockIdx.x;
    uint2 r = reinterpret_cast<const uint2*>(x + row * DQ)[threadIdx.x];
    float2 a0 = unpkh2(r.x), a1 = unpkh2(r.y);
    float v0 = a0.x, v1 = a0.y, v2 = a1.x, v3 = a1.y;
    float s = v0 + v1 + v2 + v3;
    float s2 = v0 * v0 + v1 * v1 + v2 * v2 + v3 * v3;
    block_reduce2(s, s2);
    float mean = s * (1.0f / DQ);
    float rs = rsqrtf(s2 * (1.0f / DQ) - mean * mean + 1e-5f);
    float4 wv = reinterpret_cast<const float4*>(w)[threadIdx.x];
    float4 bv = reinterpret_cast<const float4*>(bias)[threadIdx.x];
    float4 o;
    o.x = (v0 - mean) * rs * wv.x + bv.x + v0;
    o.y = (v1 - mean) * rs * wv.y + bv.y + v1;
    o.z = (v2 - mean) * rs * wv.z + bv.z + v2;
    o.w = (v3 - mean) * rs * wv.w + bv.w + v3;
    reinterpret_cast<float4*>(out + row * DQ)[threadIdx.x] = o;
}

// ---- scan: 512 threads, 4-way k split, register weights ----
__global__ __launch_bounds__(512)
void scan_kernel(const float* __restrict__ gate_w, const float* __restrict__ gate_b,
                 const float* __restrict__ state_flow, const float* __restrict__ inj,
                 __half* __restrict__ hhi, __half* __restrict__ hlo) {
    __shared__ __align__(8) float h[SQ];
    __shared__ __align__(8) unsigned long long part[512];
    const int tid = threadIdx.x;
    const int s = tid & 127;
    const int q = tid >> 7;
    const int b = blockIdx.x;

    unsigned long long wv[32];
    #pragma unroll
    for (int j = 0; j < 32; ++j) {
        int k = q * 32 + j;
        wv[j] = pk2(gate_w[s * SQ + k], state_flow[s * SQ + k]);
    }
    float gb = (q == 0) ? gate_b[s] : 0.0f;
    if (q == 0) h[s] = 0.0f;
    __syncthreads();

    const float* injb = inj + (size_t)b * TQ * SQ;
    for (int t = 0; t < TQ; ++t) {
        float injv = (q == 0) ? injb[(size_t)t * SQ + s] : 0.0f;
        unsigned long long acc2 = 0ull;
        const float2* h2 = reinterpret_cast<const float2*>(h + q * 32);
        #pragma unroll
        for (int j = 0; j < 16; ++j) {
            float2 hp = h2[j];
            fma2(acc2, pk2(hp.x, hp.x), wv[2 * j]);
            fma2(acc2, pk2(hp.y, hp.y), wv[2 * j + 1]);
        }
        part[tid] = acc2;
        __syncthreads();
        if (q == 0) {
            float2 p0 = *reinterpret_cast<float2*>(&part[s]);
            float2 p1 = *reinterpret_cast<float2*>(&part[s + 128]);
            float2 p2 = *reinterpret_cast<float2*>(&part[s + 256]);
            float2 p3 = *reinterpret_cast<float2*>(&part[s + 384]);
            float accg = p0.x + p1.x + p2.x + p3.x + gb + injv;
            float accf = p0.y + p1.y + p2.y + p3.y;
            float hold = h[s];
            float g = 1.0f / (1.0f + expf(-accg));
            float hn = (1.0f - g) * hold + g * accf;
            h[s] = hn;
            size_t off = ((size_t)(b << 10) + t) * SQ + s;
            __half hh = __float2half_rn(hn);
            hhi[off] = hh;
            hlo[off] = __float2half_rn(hn - __half2float(hh));
        }
        __syncthreads();
    }
}

// ---- narrow HMMA GEMM (128x128, 3-term, for inj) ----
#define ROWP 40
#define MATB (128 * ROWP * 2)
#define NGSM 122880

__global__ __launch_bounds__(256, 1)
void gemm_inj(const __half* __restrict__ Ahi, const __half* __restrict__ Alo,
              const __half* __restrict__ Bhi, const __half* __restrict__ Blo,
              float* __restrict__ outf, int K, int N) {
    constexpr int NSTG = 3;
    constexpr int STGB = 4 * MATB;
    extern __shared__ __align__(16) unsigned char dsm[];
    const uint32_t sbase = smem_u32(dsm);
    const int tid = threadIdx.x, lane = tid & 31, wid = tid >> 5;
    const size_t mBase = (size_t)blockIdx.y * 128, nBase = (size_t)blockIdx.x * 128;

    const int lrow = tid >> 1, lchunk = (tid & 1) * 2;
    const size_t aoff = (mBase + lrow) * (size_t)K + lchunk * 8;
    const size_t boff = (nBase + lrow) * (size_t)K + lchunk * 8;
    const uint32_t soff = (uint32_t)(lrow * 80 + lchunk * 16);
    const int ktiles = K / 32;

    auto issue = [&](int st, int kt) {
        uint32_t sb = sbase + (uint32_t)st * STGB;
        size_t k0 = (size_t)kt * 32;
        const __half* pa = Ahi + aoff + k0;
        const __half* pb = Alo + aoff + k0;
        const __half* pc = Bhi + boff + k0;
        const __half* pd = Blo + boff + k0;
        cpa16(sb + soff,            pa);  cpa16(sb + soff + 16,            pa + 8);
        cpa16(sb + MATB + soff,     pb);  cpa16(sb + MATB + soff + 16,     pb + 8);
        cpa16(sb + 2 * MATB + soff, pc);  cpa16(sb + 2 * MATB + soff + 16, pc + 8);
        cpa16(sb + 3 * MATB + soff, pd);  cpa16(sb + 3 * MATB + soff + 16, pd + 8);
        asm volatile("cp.async.commit_group;" ::: "memory");
    };
    for (int s = 0; s < 2; ++s) issue(s, s);

    const int wy = wid >> 2, wx = wid & 3;
    const int m_w = wy * 64, n_w = wx * 32;
    float acc[4][4][4];
    #pragma unroll
    for (int i = 0; i < 4; ++i)
        #pragma unroll
        for (int j = 0; j < 4; ++j)
            #pragma unroll
            for (int e = 0; e < 4; ++e) acc[i][j][e] = 0.0f;

    for (int kt = 0; kt < ktiles; ++kt) {
        if (ktiles - 1 - kt >= 1) wgrp<1>(); else wgrp<0>();
        __syncthreads();
        if (kt + 2 < ktiles) issue((kt + 2) % NSTG, kt + 2);
        const uint32_t sb = sbase + (uint32_t)(kt % NSTG) * STGB;
        const uint32_t sAh = sb, sAl = sb + MATB, sBh = sb + 2 * MATB, sBl = sb + 3 * MATB;
        #pragma unroll
        for (int kk = 0; kk < 2; ++kk) {
            const int kc = kk * 16;
            const int arow = (lane & 15);
            const int acol = kc + ((lane >> 4) << 3);
            const int brow = (lane & 7) + ((lane >> 4) << 3);
            const int bcol = kc + (lane & 8);
            uint32_t ah[4][4], al[4][4], bh[4][2], bl[4][2];
            #pragma unroll
            for (int mf = 0; mf < 4; ++mf) {
                uint32_t a = (uint32_t)((m_w + mf * 16 + arow) * ROWP + acol) * 2;
                ldsm4(ah[mf][0], ah[mf][1], ah[mf][2], ah[mf][3], sAh + a);
                ldsm4(al[mf][0], al[mf][1], al[mf][2], al[mf][3], sAl + a);
            }
            #pragma unroll
            for (int g = 0; g < 2; ++g) {
                uint32_t a = (uint32_t)((n_w + g * 16 + brow) * ROWP + bcol) * 2;
                uint32_t r0, r1, r2, r3;
                ldsm4(r0, r1, r2, r3, sBh + a);
                bh[g * 2][0] = r0; bh[g * 2][1] = r1; bh[g * 2 + 1][0] = r2; bh[g * 2 + 1][1] = r3;
                ldsm4(r0, r1, r2, r3, sBl + a);
                bl[g * 2][0] = r0; bl[g * 2][1] = r1; bl[g * 2 + 1][0] = r2; bl[g * 2 + 1][1] = r3;
            }
            #pragma unroll
            for (int mf = 0; mf < 4; ++mf)
                #pragma unroll
                for (int nf = 0; nf < 4; ++nf) {
                    mma16816(acc[mf][nf], ah[mf], bh[nf]);
                    mma16816(acc[mf][nf], al[mf], bh[nf]);
                    mma16816(acc[mf][nf], ah[mf], bl[nf]);
                }
        }
        __syncthreads();
    }
    #pragma unroll
    for (int mf = 0; mf < 4; ++mf)
        #pragma unroll
        for (int nf = 0; nf < 4; ++nf) {
            size_t r0 = mBase + m_w + mf * 16 + (lane >> 2);
            size_t cc = nBase + n_w + nf * 8 + (lane & 3) * 2;
            float2 s0 = { acc[mf][nf][0], acc[mf][nf][1] };
            float2 s1 = { acc[mf][nf][2], acc[mf][nf][3] };
            *reinterpret_cast<float2*>(outf + r0 * N + cc) = s0;
            *reinterpret_cast<float2*>(outf + (r0 + 8) * N + cc) = s1;
        }
}

// ---- x2 GEMM (128x256, 2-term A, K=128): + (lnx_hi+lnx_lo), store hi ----
#define W_AB 10240
#define X2SMEM (4 * 4 * W_AB)

__global__ __launch_bounds__(256, 1)
void gemm_x2(const __half* __restrict__ Ahi, const __half* __restrict__ Alo,
             const __half* __restrict__ Bhi,
             const __half* __restrict__ exh, const __half* __restrict__ exl,
             __half* __restrict__ ohi, int K, int N) {
    constexpr int NSTG = 4;
    constexpr int STGB = 4 * W_AB;
    extern __shared__ __align__(16) unsigned char dsm[];
    const uint32_t sbase = smem_u32(dsm);
    const int tid = threadIdx.x, lane = tid & 31, wid = tid >> 5;
    const size_t mBase = (size_t)blockIdx.y * 128, nBase = (size_t)blockIdx.x * 256;

    const int lrow = tid >> 1, lchunk = (tid & 1) * 2;
    const size_t aoff  = (mBase + lrow) * (size_t)K + lchunk * 8;
    const size_t boff0 = (nBase + lrow) * (size_t)K + lchunk * 8;
    const size_t boff1 = (nBase + lrow + 128) * (size_t)K + lchunk * 8;
    const uint32_t soff  = (uint32_t)(lrow * 80 + lchunk * 16);
    const uint32_t soff1 = (uint32_t)((lrow + 128) * 80 + lchunk * 16);
    const int ktiles = K / 32;

    auto issue = [&](int st, int kt) {
        uint32_t sb = sbase + (uint32_t)st * STGB;
        size_t k0 = (size_t)kt * 32;
        const __half* pa = Ahi + aoff + k0;
        const __half* pb = Alo + aoff + k0;
        const __half* pc = Bhi + boff0 + k0;
        const __half* pd = Bhi + boff1 + k0;
        cpa16(sb + soff,            pa);  cpa16(sb + soff + 16,            pa + 8);
        cpa16(sb + W_AB + soff,     pb);  cpa16(sb + W_AB + soff + 16,     pb + 8);
        cpa16(sb + 2 * W_AB + soff, pc);  cpa16(sb + 2 * W_AB + soff + 16, pc + 8);
        cpa16(sb + 2 * W_AB + soff1, pd); cpa16(sb + 2 * W_AB + soff1 + 16, pd + 8);
        asm volatile("cp.async.commit_group;" ::: "memory");
    };
    const int npre = ktiles < 3 ? ktiles : 3;
    for (int s = 0; s < npre; ++s) issue(s, s);

    const int wy = wid >> 2, wx = wid & 3;
    const int m_w = wy * 64, n_w = wx * 64;

    float acc[4][8][4];
    #pragma unroll
    for (int i = 0; i < 4; ++i)
        #pragma unroll
        for (int j = 0; j < 8; ++j)
            #pragma unroll
            for (int e = 0; e < 4; ++e) acc[i][j][e] = 0.0f;

    for (int kt = 0; kt < ktiles; ++kt) {
        const int rem = ktiles - 1 - kt;
        if (rem >= 2) wgrp<2>(); else if (rem == 1) wgrp<1>(); else wgrp<0>();
        __syncthreads();
        if (kt + 3 < ktiles) issue((kt + 3) % NSTG, kt + 3);

        const uint32_t sb = sbase + (uint32_t)(kt % NSTG) * STGB;
        const uint32_t sAh = sb, sAl = sb + W_AB, sBh = sb + 2 * W_AB;

        #pragma unroll
        for (int kk = 0; kk < 2; ++kk) {
            const int kc = kk * 16;
            const int arow = (lane & 15);
            const int acol = kc + ((lane >> 4) << 3);
            const int brow = (lane & 7) + ((lane >> 4) << 3);
            const int bcol = kc + (lane & 8);
            uint32_t ah[4][4], al[4][4], bh[8][2];
            #pragma unroll
            for (int mf = 0; mf < 4; ++mf) {
                uint32_t a = (uint32_t)((m_w + mf * 16 + arow) * ROWP + acol) * 2;
                ldsm4(ah[mf][0], ah[mf][1], ah[mf][2], ah[mf][3], sAh + a);
                ldsm4(al[mf][0], al[mf][1], al[mf][2], al[mf][3], sAl + a);
            }
            #pragma unroll
            for (int g = 0; g < 4; ++g) {
                uint32_t a = (uint32_t)((n_w + g * 16 + brow) * ROWP + bcol) * 2;
                uint32_t r0, r1, r2, r3;
                ldsm4(r0, r1, r2, r3, sBh + a);
                bh[g * 2][0] = r0; bh[g * 2][1] = r1; bh[g * 2 + 1][0] = r2; bh[g * 2 + 1][1] = r3;
            }
            #pragma unroll
            for (int mf = 0; mf < 4; ++mf)
                #pragma unroll
                for (int nf = 0; nf < 8; ++nf) {
                    mma16816(acc[mf][nf], ah[mf], bh[nf]);
                    mma16816(acc[mf][nf], al[mf], bh[nf]);
                }
        }
        __syncthreads();
    }

    #pragma unroll
    for (int mf = 0; mf < 4; ++mf) {
        #pragma unroll
        for (int nf = 0; nf < 8; ++nf) {
            size_t r0 = mBase + m_w + mf * 16 + (lane >> 2);
            size_t cc = nBase + n_w + nf * 8 + (lane & 3) * 2;
            float2 e0h = unpkh2(*reinterpret_cast<const uint32_t*>(exh + r0 * N + cc));
            float2 e0l = unpkh2(*reinterpret_cast<const uint32_t*>(exl + r0 * N + cc));
            float2 e1h = unpkh2(*reinterpret_cast<const uint32_t*>(exh + (r0 + 8) * N + cc));
            float2 e1l = unpkh2(*reinterpret_cast<const uint32_t*>(exl + (r0 + 8) * N + cc));
            float v0 = acc[mf][nf][0] + e0h.x + e0l.x;
            float v1 = acc[mf][nf][1] + e0h.y + e0l.y;
            float v2 = acc[mf][nf][2] + e1h.x + e1l.x;
            float v3 = acc[mf][nf][3] + e1h.y + e1l.y;
            *reinterpret_cast<uint32_t*>(ohi + r0 * N + cc) = pkh2(v0, v1);
            *reinterpret_cast<uint32_t*>(ohi + (r0 + 8) * N + cc) = pkh2(v2, v3);
        }
    }
}

// ---- 1-term HMMA GEMM (128x128 tile, 3 stages, 2 CTAs/SM), fp16 out ----
#define G1_STG (2 * W_AB)
#define G1_SMEM (3 * G1_STG)   // 61440

template <bool GELU>
__global__ __launch_bounds__(256, 2)
void gemm1(const __half* __restrict__ A, const __half* __restrict__ B,
           const float* __restrict__ ext, __half* __restrict__ ohi, int K, int N) {
    constexpr int NSTG = 3;
    extern __shared__ __align__(16) unsigned char dsm[];
    const uint32_t sbase = smem_u32(dsm);
    const int tid = threadIdx.x, lane = tid & 31, wid = tid >> 5;
    const size_t mBase = (size_t)blockIdx.y * 128, nBase = (size_t)blockIdx.x * 128;

    const int lrow = tid >> 1, lchunk = (tid & 1) * 2;
    const size_t aoff = (mBase + lrow) * (size_t)K + lchunk * 8;
    const size_t boff = (nBase + lrow) * (size_t)K + lchunk * 8;
    const uint32_t soff = (uint32_t)(lrow * 80 + lchunk * 16);
    const int ktiles = K / 32;

    auto issue = [&](int st, int kt) {
        uint32_t sb = sbase + (uint32_t)st * G1_STG;
        size_t k0 = (size_t)kt * 32;
        const __half* pa = A + aoff + k0;
        const __half* pb = B + boff + k0;
        cpa16(sb + soff,        pa);  cpa16(sb + soff + 16,        pa + 8);
        cpa16(sb + W_AB + soff, pb);  cpa16(sb + W_AB + soff + 16, pb + 8);
        asm volatile("cp.async.commit_group;" ::: "memory");
    };
    for (int s = 0; s < 2; ++s) issue(s, s);

    const int wy = wid >> 2, wx = wid & 3;
    const int m_w = wy * 64, n_w = wx * 32;

    float acc[4][4][4];
    #pragma unroll
    for (int i = 0; i < 4; ++i)
        #pragma unroll
        for (int j = 0; j < 4; ++j)
            #pragma unroll
            for (int e = 0; e < 4; ++e) acc[i][j][e] = 0.0f;

    for (int kt = 0; kt < ktiles; ++kt) {
        if (ktiles - 1 - kt >= 1) wgrp<1>(); else wgrp<0>();
        __syncthreads();
        if (kt + 2 < ktiles) issue((kt + 2) % NSTG, kt + 2);

        const uint32_t sb = sbase + (uint32_t)(kt % NSTG) * G1_STG;
        const uint32_t sA = sb, sB = sb + W_AB;

        #pragma unroll
        for (int kk = 0; kk < 2; ++kk) {
            const int kc = kk * 16;
            const int arow = (lane & 15);
            const int acol = kc + ((lane >> 4) << 3);
            const int brow = (lane & 7) + ((lane >> 4) << 3);
            const int bcol = kc + (lane & 8);
            uint32_t ah[4][4], bh[4][2];
            #pragma unroll
            for (int mf = 0; mf < 4; ++mf) {
                uint32_t a = (uint32_t)((m_w + mf * 16 + arow) * ROWP + acol) * 2;
                ldsm4(ah[mf][0], ah[mf][1], ah[mf][2], ah[mf][3], sA + a);
            }
            #pragma unroll
            for (int g = 0; g < 2; ++g) {
                uint32_t a = (uint32_t)((n_w + g * 16 + brow) * ROWP + bcol) * 2;
                uint32_t r0, r1, r2, r3;
                ldsm4(r0, r1, r2, r3, sB + a);
                bh[g * 2][0] = r0; bh[g * 2][1] = r1; bh[g * 2 + 1][0] = r2; bh[g * 2 + 1][1] = r3;
            }
            #pragma unroll
            for (int mf = 0; mf < 4; ++mf)
                #pragma unroll
                for (int nf = 0; nf < 4; ++nf)
                    mma16816(acc[mf][nf], ah[mf], bh[nf]);
        }
        __syncthreads();
    }

    #pragma unroll
    for (int mf = 0; mf < 4; ++mf) {
        #pragma unroll
        for (int nf = 0; nf < 4; ++nf) {
            size_t r0 = mBase + m_w + mf * 16 + (lane >> 2);
            size_t cc = nBase + n_w + nf * 8 + (lane & 3) * 2;
            float2 bb = *reinterpret_cast<const float2*>(ext + cc);
            float v0 = acc[mf][nf][0] + bb.x, v1 = acc[mf][nf][1] + bb.y;
            float v2 = acc[mf][nf][2] + bb.x, v3 = acc[mf][nf][3] + bb.y;
            if (GELU) {
                v0 = gelu_exact(v0); v1 = gelu_exact(v1);
                v2 = gelu_exact(v2); v3 = gelu_exact(v3);
            }
            *reinterpret_cast<uint32_t*>(ohi + r0 * N + cc) = pkh2(v0, v1);
            *reinterpret_cast<uint32_t*>(ohi + (r0 + 8) * N + cc) = pkh2(v2, v3);
        }
    }
}

// ---- launch ----
extern "C" void kernel_launch(void* const* d_in, const int* in_sizes, int n_in,
                              void* d_out, int out_size) {
    const float* x          = (const float*)d_in[0];
    const float* ln1_w      = (const float*)d_in[1];
    const float* ln1_b      = (const float*)d_in[2];
    const float* state_flow = (const float*)d_in[3];
    const float* injection  = (const float*)d_in[4];
    const float* readout    = (const float*)d_in[5];
    const float* gate_w     = (const float*)d_in[6];
    const float* gate_b     = (const float*)d_in[7];
    const float* w1         = (const float*)d_in[8];
    const float* b1         = (const float*)d_in[9];
    const float* w2         = (const float*)d_in[10];
    const float* b2         = (const float*)d_in[11];
    const float* ln2_w      = (const float*)d_in[12];
    const float* ln2_b      = (const float*)d_in[13];
    float* out = (float*)d_out;

    float *inj;
    __half *lnxh, *lnxl, *hh, *hl, *x2h, *hbh, *x3h;
    __half *wih, *wil, *roh, *w1h, *w2h;
    cudaGetSymbolAddress((void**)&lnxh, g_lnx_hi);
    cudaGetSymbolAddress((void**)&lnxl, g_lnx_lo);
    cudaGetSymbolAddress((void**)&inj, g_inj);
    cudaGetSymbolAddress((void**)&hh, g_h_hi);
    cudaGetSymbolAddress((void**)&hl, g_h_lo);
    cudaGetSymbolAddress((void**)&x2h, g_x2_hi);
    cudaGetSymbolAddress((void**)&hbh, g_hb_hi);
    cudaGetSymbolAddress((void**)&x3h, g_x3_hi);
    cudaGetSymbolAddress((void**)&wih, g_wi_hi);
    cudaGetSymbolAddress((void**)&wil, g_wi_lo);
    cudaGetSymbolAddress((void**)&roh, g_ro_hi);
    cudaGetSymbolAddress((void**)&w1h, g_w1_hi);
    cudaGetSymbolAddress((void**)&w2h, g_w2_hi);

    cudaFuncSetAttribute(gemm_inj,     cudaFuncAttributeMaxDynamicSharedMemorySize, NGSM);
    cudaFuncSetAttribute(gemm_x2,      cudaFuncAttributeMaxDynamicSharedMemorySize, X2SMEM);
    cudaFuncSetAttribute(gemm1<true>,  cudaFuncAttributeMaxDynamicSharedMemorySize, G1_SMEM);
    cudaFuncSetAttribute(gemm1<false>, cudaFuncAttributeMaxDynamicSharedMemorySize, G1_SMEM);

    // weight conversions
    conv_split<<<(SQ * DQ / 8) / 256, 256>>>(injection, wih, wil);
    conv_hi<<<(DQ * SQ / 8) / 256, 256>>>(readout, roh);
    conv_hi<<<(int)(((size_t)HQ * DQ / 8) / 256), 256>>>(w1, w1h);
    conv_hi<<<(int)(((size_t)DQ * HQ / 8) / 256), 256>>>(w2, w2h);
    // LN1 -> hi/lo
    ln1_kernel<<<MQ, 256>>>(x, ln1_w, ln1_b, lnxh, lnxl);
    // inj = lnx @ injection^T  (3-term)
    gemm_inj<<<dim3(1, MQ / 128), 256, NGSM>>>(lnxh, lnxl, wih, wil, inj, DQ, SQ);
    // scan -> h hi/lo
    scan_kernel<<<BQ, 512>>>(gate_w, gate_b, state_flow, inj, hh, hl);
    // x2 = (lnx_hi+lnx_lo) + h @ readout^T  (2-term A, 128x256, 1 CTA/SM)
    gemm_x2<<<dim3(DQ / 256, MQ / 128), 256, X2SMEM>>>(hh, hl, roh, lnxh, lnxl, x2h, SQ, DQ);
    // hb = gelu(x2 @ w1^T + b1)  (1-term, 3 stages, 2 CTA/SM)
    gemm1<true><<<dim3(HQ / 128, MQ / 128), 256, G1_SMEM>>>(x2h, w1h, b1, hbh, DQ, HQ);
    // x3 = hb @ w2^T + b2        (1-term, fp16 store)
    gemm1<false><<<dim3(DQ / 128, MQ / 128), 256, G1_SMEM>>>(hbh, w2h, b2, x3h, HQ, DQ);
    // out = x3 + LN(x3)
    ln2_kernel<<<MQ, 256>>>(x3h, ln2_w, ln2_b, out);
}